// round 15
// baseline (speedup 1.0000x reference)
#include <cuda_runtime.h>

// Problem constants (from reference setup_inputs)
#define NB 8192
#define NK 512
#define NC 16

#define THREADS 128                          // smaller CTAs -> finer SM balance
#define GROUPS_PER_BLOCK (THREADS / NC)      // 8 examples per block
#define GRID (NB / GROUPS_PER_BLOCK)         // 1024 blocks (6.92 CTA/SM, ~1% imbalance)
#define NWARPS (THREADS / 32)                // 4

__device__ float    g_partials[GRID];
__device__ unsigned g_ticket = 0;            // atomicInc wraps to 0 each launch

// One 16-thread group per example b; lane c handles candidate c.
// Search = 9-probe serial scalar binary search (the measured-floor pattern).
__global__ void __launch_bounds__(THREADS) roc_fused_kernel(
    const float* __restrict__ logits,   // [B, K, C]
    const int*   __restrict__ target,   // [B]
    const int*   __restrict__ mask,     // [B, C, K] leading-ones rows
    float*       __restrict__ out)
{
    const int tid = blockIdx.x * THREADS + threadIdx.x;
    const int b = tid >> 4;
    const int c = tid & 15;

    const int tgt = __ldg(target + b);  // tiny, in flight during the search

    // ---- binary search for last k with mask==1 (mask[...,0]==1 guaranteed) ----
    const int* m = mask + ((size_t)b * NC + c) * NK;
    int lo = 0, hi = NK - 1;
    #pragma unroll
    for (int it = 0; it < 9; ++it) {     // 2^9 = 512 -> lo==hi after 9 steps
        int mid = (lo + hi + 1) >> 1;
        if (__ldg(m + mid)) lo = mid; else hi = mid - 1;
    }
    const int counter = lo;              // lengths-1

    // ---- gather logit at last valid timestep ----
    const float x = __ldg(logits + ((size_t)b * NK + counter) * NC + c);

    // ---- log-softmax over the 16 candidates (width-16, all lanes active) ----
    const unsigned FULL = 0xffffffffu;
    float mx = x;
    #pragma unroll
    for (int o = 8; o; o >>= 1) mx = fmaxf(mx, __shfl_xor_sync(FULL, mx, o, 16));
    float s = __expf(x - mx);
    #pragma unroll
    for (int o = 8; o; o >>= 1) s += __shfl_xor_sync(FULL, s, o, 16);

    const float xt = __shfl_sync(FULL, x, tgt, 16);  // lane tgt within segment
    const float loss = __logf(s) + mx - xt;           // logsumexp - x[target]

    // ---- deterministic block reduction (one loss per 16-lane group) ----
    float vsum = (c == 0) ? loss : 0.0f;
    #pragma unroll
    for (int o = 16; o; o >>= 1) vsum += __shfl_xor_sync(FULL, vsum, o);

    __shared__ float ssum[NWARPS];
    __shared__ bool  s_last;
    const int warp = threadIdx.x >> 5;
    if ((threadIdx.x & 31) == 0) ssum[warp] = vsum;
    __syncthreads();
    if (threadIdx.x < NWARPS) {
        // EXACT mask (0xF): lanes 4-31 proceed to the __syncthreads below.
        float wv = ssum[threadIdx.x];
        #pragma unroll
        for (int o = NWARPS / 2; o; o >>= 1)
            wv += __shfl_xor_sync(0xFu, wv, o, NWARPS);
        if (threadIdx.x == 0) g_partials[blockIdx.x] = wv;
    }

    // ---- last block takes the ticket, does the final fixed-order reduce ----
    if (threadIdx.x == 0) {
        __threadfence();                                  // publish partial
        unsigned t = atomicInc(&g_ticket, GRID - 1);      // wraps to 0: replay-safe
        s_last = (t == GRID - 1);
    }
    __syncthreads();
    if (s_last) {
        __threadfence();                                  // acquire partials
        float r = 0.0f;
        #pragma unroll
        for (int j = 0; j < GRID / THREADS; ++j)          // 8 partials per thread,
            r += g_partials[threadIdx.x + j * THREADS];   // fixed order
        #pragma unroll
        for (int o = 16; o; o >>= 1) r += __shfl_xor_sync(FULL, r, o);
        if ((threadIdx.x & 31) == 0) ssum[warp] = r;
        __syncthreads();
        if (threadIdx.x < NWARPS) {
            float wv = ssum[threadIdx.x];
            #pragma unroll
            for (int o = NWARPS / 2; o; o >>= 1)
                wv += __shfl_xor_sync(0xFu, wv, o, NWARPS);
            if (threadIdx.x == 0) out[0] = wv * (1.0f / (float)NB);
        }
    }
}

extern "C" void kernel_launch(void* const* d_in, const int* in_sizes, int n_in,
                              void* d_out, int out_size)
{
    const float* logits = (const float*)d_in[0];
    const int*   target = (const int*)  d_in[1];
    const int*   mask   = (const int*)  d_in[2];
    float* out = (float*)d_out;

    roc_fused_kernel<<<GRID, THREADS>>>(logits, target, mask, out);
}

// round 17
// speedup vs baseline: 1.0200x; 1.0200x over previous
#include <cuda_runtime.h>

// Problem constants (from reference setup_inputs)
#define NB 8192
#define NK 512
#define NC 16

#define THREADS 256
#define GROUPS_PER_BLOCK (THREADS / NC)      // 16 examples per block
#define GRID (NB / GROUPS_PER_BLOCK)         // 512 blocks
#define NWARPS (THREADS / 32)                // 8

__device__ float    g_partials[GRID];
__device__ unsigned g_ticket = 0;            // atomicInc wraps to 0 each launch

// One 16-thread group per example b; lane c handles candidate c.
// 64B-granule search (HBM DRAM granule): 5 serial scalar probes over the 32
// granule-heads (16 ints each), then 4 scalar probes INSIDE the winning
// granule (L1-resident after the head fetch), then 1 logit gather.
// 6 distinct DRAM granules/row — the minimum of the all-scalar family that
// has measured fastest across 15 rounds (12.8us plateau).
__global__ void __launch_bounds__(THREADS) roc_fused_kernel(
    const float* __restrict__ logits,   // [B, K, C]
    const int*   __restrict__ target,   // [B]
    const int*   __restrict__ mask,     // [B, C, K] leading-ones rows
    float*       __restrict__ out)
{
    const int tid = blockIdx.x * THREADS + threadIdx.x;
    const int b = tid >> 4;
    const int c = tid & 15;

    const int tgt = __ldg(target + b);  // tiny, in flight during the search

    // ---- stage 1: last 64B granule g in [0,32) with head m[16g]==1 ----
    // Row is a leading-ones run; m[0]==1 guaranteed (lengths >= 1).
    const int* m = mask + ((size_t)b * NC + c) * NK;
    int g = 0;
    #pragma unroll
    for (int span = 16; span; span >>= 1) {       // 5 serial scalar probes
        int mid = g + span;
        if (__ldg(m + (mid << 4))) g = mid;
    }
    // ---- stage 2: boundary within granule g (16 ints, 64B; L1-resident) ----
    int p = g << 4;                               // m[p]==1 by invariant
    #pragma unroll
    for (int span = 8; span; span >>= 1) {        // 4 scalar probes, same granule
        if (__ldg(m + p + span)) p += span;
    }
    const int counter = p;                        // lengths-1

    // ---- gather logit at last valid timestep (1 granule) ----
    const float x = __ldg(logits + ((size_t)b * NK + counter) * NC + c);

    // ---- log-softmax over the 16 candidates (width-16, all lanes active) ----
    const unsigned FULL = 0xffffffffu;
    float mx = x;
    #pragma unroll
    for (int o = 8; o; o >>= 1) mx = fmaxf(mx, __shfl_xor_sync(FULL, mx, o, 16));
    float s = __expf(x - mx);
    #pragma unroll
    for (int o = 8; o; o >>= 1) s += __shfl_xor_sync(FULL, s, o, 16);

    const float xt = __shfl_sync(FULL, x, tgt, 16);  // lane tgt within segment
    const float loss = __logf(s) + mx - xt;           // logsumexp - x[target]

    // ---- deterministic block reduction (one loss per 16-lane group) ----
    float vsum = (c == 0) ? loss : 0.0f;
    #pragma unroll
    for (int o = 16; o; o >>= 1) vsum += __shfl_xor_sync(FULL, vsum, o);

    __shared__ float ssum[NWARPS];
    __shared__ bool  s_last;
    const int warp = threadIdx.x >> 5;
    if ((threadIdx.x & 31) == 0) ssum[warp] = vsum;
    __syncthreads();
    if (threadIdx.x < NWARPS) {
        // EXACT mask (0xFF): lanes 8-31 proceed to the __syncthreads below.
        float wv = ssum[threadIdx.x];
        #pragma unroll
        for (int o = NWARPS / 2; o; o >>= 1)
            wv += __shfl_xor_sync(0xFFu, wv, o, NWARPS);
        if (threadIdx.x == 0) g_partials[blockIdx.x] = wv;
    }

    // ---- last block takes the ticket, does the final fixed-order reduce ----
    if (threadIdx.x == 0) {
        __threadfence();                                  // publish partial
        unsigned t = atomicInc(&g_ticket, GRID - 1);      // wraps to 0: replay-safe
        s_last = (t == GRID - 1);
    }
    __syncthreads();
    if (s_last) {
        __threadfence();                                  // acquire partials
        float r = g_partials[threadIdx.x] + g_partials[threadIdx.x + THREADS];
        #pragma unroll
        for (int o = 16; o; o >>= 1) r += __shfl_xor_sync(FULL, r, o);
        if ((threadIdx.x & 31) == 0) ssum[warp] = r;
        __syncthreads();
        if (threadIdx.x < NWARPS) {
            float wv = ssum[threadIdx.x];
            #pragma unroll
            for (int o = NWARPS / 2; o; o >>= 1)
                wv += __shfl_xor_sync(0xFFu, wv, o, NWARPS);
            if (threadIdx.x == 0) out[0] = wv * (1.0f / (float)NB);
        }
    }
}

extern "C" void kernel_launch(void* const* d_in, const int* in_sizes, int n_in,
                              void* d_out, int out_size)
{
    const float* logits = (const float*)d_in[0];
    const int*   target = (const int*)  d_in[1];
    const int*   mask   = (const int*)  d_in[2];
    float* out = (float*)d_out;

    roc_fused_kernel<<<GRID, THREADS>>>(logits, target, mask, out);
}